// round 2
// baseline (speedup 1.0000x reference)
#include <cuda_runtime.h>
#include <math.h>

#define NN 100000
#define NP 5000
#define NE 1000000
#define DA 20

// ---------------- scratch (device globals; no allocation) ----------------
__device__ float g_keys[NN * DA];       // 8 MB
__device__ float g_query[NP * DA];
__device__ int   g_cnt[NP];
__device__ int   g_rowptr[NP + 1];
__device__ int   g_fill[NP];
__device__ int   g_ssrc[NE];            // 4 MB
__device__ float g_satt[NE];            // 4 MB
__device__ float g_agg[NP * 128];
__device__ float g_attsum[NP];
__device__ float g_ws[NP * 128];
__device__ float g_gi[NP * 384];
__device__ float g_gh[NP * 384];

// ---------------- small-N projection: out[M x 20] = A[M x K] @ W[K x 20] + b
// KDIM==128 -> keys (out=g_keys), KDIM==256 -> query (out=g_query, A split A0/A1)
template <int KDIM>
__global__ __launch_bounds__(128) void proj_kernel(
    const float* __restrict__ A0, const float* __restrict__ A1,
    const float* __restrict__ W, const float* __restrict__ bias, int M)
{
    __shared__ alignas(16) float sW[KDIM * DA];
    __shared__ alignas(16) float sA[128 * 36];
    float* __restrict__ out = (KDIM == 128) ? g_keys : g_query;

    int tid = threadIdx.x;
    for (int i = tid; i < KDIM * DA; i += 128) sW[i] = W[i];

    float acc[DA];
#pragma unroll
    for (int c = 0; c < DA; c++) acc[c] = bias[c];

    int r0 = blockIdx.x * 128;
    int row = r0 + tid;

#pragma unroll 1
    for (int kc = 0; kc < KDIM; kc += 32) {
        const float* Asrc = (kc < 128) ? A0 : A1;
        int kbase = (kc < 128) ? kc : kc - 128;
        __syncthreads();
        int c = tid & 31, rb = tid >> 5;
#pragma unroll
        for (int i = 0; i < 32; i++) {
            int rr = rb + i * 4;
            int gr = r0 + rr;
            sA[rr * 36 + c] = (gr < M) ? Asrc[gr * 128 + kbase + c] : 0.f;
        }
        __syncthreads();
        float a[32];
#pragma unroll
        for (int j = 0; j < 8; j++) {
            float4 v = *reinterpret_cast<const float4*>(&sA[tid * 36 + 4 * j]);
            a[4 * j + 0] = v.x; a[4 * j + 1] = v.y;
            a[4 * j + 2] = v.z; a[4 * j + 3] = v.w;
        }
#pragma unroll
        for (int kk = 0; kk < 32; kk++) {
            const float* wr = &sW[(kc + kk) * DA];
            float av = a[kk];
#pragma unroll
            for (int j = 0; j < 5; j++) {
                float4 w = *reinterpret_cast<const float4*>(wr + 4 * j);
                acc[4 * j + 0] = fmaf(av, w.x, acc[4 * j + 0]);
                acc[4 * j + 1] = fmaf(av, w.y, acc[4 * j + 1]);
                acc[4 * j + 2] = fmaf(av, w.z, acc[4 * j + 2]);
                acc[4 * j + 3] = fmaf(av, w.w, acc[4 * j + 3]);
            }
        }
    }
    if (row < M) {
#pragma unroll
        for (int j = 0; j < 5; j++) {
            float4 v = make_float4(acc[4 * j], acc[4 * j + 1], acc[4 * j + 2], acc[4 * j + 3]);
            *reinterpret_cast<float4*>(&out[row * DA + 4 * j]) = v;
        }
    }
}

// ---------------- CSR build ----------------
__global__ void zero_cnt_kernel()
{
    int i = blockIdx.x * blockDim.x + threadIdx.x;
    if (i < NP) g_cnt[i] = 0;
}

__global__ void count_kernel(const int* __restrict__ dst)
{
    int i = blockIdx.x * blockDim.x + threadIdx.x;
    if (i < NE) atomicAdd(&g_cnt[dst[i]], 1);
}

__global__ __launch_bounds__(1024) void scan_kernel()
{
    __shared__ int ss[1024];
    int tid = threadIdx.x;
    const int BP = 5;                 // 1024*5 >= NP
    int base = tid * BP;
    int loc[BP];
    int s = 0;
#pragma unroll
    for (int i = 0; i < BP; i++) {
        int b = base + i;
        loc[i] = (b < NP) ? g_cnt[b] : 0;
        s += loc[i];
    }
    ss[tid] = s;
    __syncthreads();
    for (int off = 1; off < 1024; off <<= 1) {
        int add = (tid >= off) ? ss[tid - off] : 0;
        __syncthreads();
        ss[tid] += add;
        __syncthreads();
    }
    int run = ss[tid] - s;            // exclusive prefix
#pragma unroll
    for (int i = 0; i < BP; i++) {
        int b = base + i;
        if (b < NP) { g_rowptr[b] = run; g_fill[b] = run; run += loc[i]; }
    }
    if (tid == 1023) g_rowptr[NP] = ss[1023];
}

// ---------------- per-edge attention + bucket scatter ----------------
__global__ void att_scatter_kernel(const int* __restrict__ src, const int* __restrict__ dst)
{
    int i = blockIdx.x * blockDim.x + threadIdx.x;
    if (i >= NE) return;
    int s = src[i], d = dst[i];
    const float4* kr = reinterpret_cast<const float4*>(g_keys + s * DA);
    const float4* qr = reinterpret_cast<const float4*>(g_query + d * DA);
    float sum = 0.f;
#pragma unroll
    for (int j = 0; j < 5; j++) {
        float4 a = kr[j], b = qr[j];
        sum += a.x * b.x + a.y * b.y + a.z * b.z + a.w * b.w;
    }
    sum *= 0.2236067977499789696f;    // 1/sqrt(20)
    int pos = atomicAdd(&g_fill[d], 1);
    g_ssrc[pos] = s;
    g_satt[pos] = sum;
}

// ---------------- aggregation in node basis: agg[p] = sum att*nodes[src] ----
__global__ __launch_bounds__(128) void aggregate_kernel(const float* __restrict__ nodes)
{
    int p = blockIdx.x;
    int tid = threadIdx.x;
    int beg = g_rowptr[p], end = g_rowptr[p + 1];
    float acc = 0.f, asum = 0.f;
    int i = beg;
    for (; i + 4 <= end; i += 4) {
        int s0 = g_ssrc[i], s1 = g_ssrc[i + 1], s2 = g_ssrc[i + 2], s3 = g_ssrc[i + 3];
        float a0 = g_satt[i], a1 = g_satt[i + 1], a2 = g_satt[i + 2], a3 = g_satt[i + 3];
        float v0 = nodes[s0 * 128 + tid];
        float v1 = nodes[s1 * 128 + tid];
        float v2 = nodes[s2 * 128 + tid];
        float v3 = nodes[s3 * 128 + tid];
        acc = fmaf(a0, v0, acc); acc = fmaf(a1, v1, acc);
        acc = fmaf(a2, v2, acc); acc = fmaf(a3, v3, acc);
        asum += (a0 + a1) + (a2 + a3);
    }
    for (; i < end; i++) {
        int s = g_ssrc[i];
        float a = g_satt[i];
        acc = fmaf(a, nodes[s * 128 + tid], acc);
        asum += a;
    }
    g_agg[p * 128 + tid] = acc;
    if (tid == 0) g_attsum[p] = asum;
}

// ---------------- SGEMM: C[M x N] = A[M x 128] @ B (+bias, +rowscale*rowvec)
// MODE 0: A=g_agg, B=val_W [128x128] (K-major), C=g_ws, rowscale=attsum, rowvec=val_b
// MODE 1: A=g_ws,  B=W_ih  [384x128] (N-major), C=g_gi, bias=b_ih
// MODE 2: A=param, B=W_hh  [384x128] (N-major), C=g_gh, bias=b_hh
template <int MODE>
__global__ __launch_bounds__(256) void sgemm_kernel(
    const float* __restrict__ Aparam, const float* __restrict__ B,
    const float* __restrict__ bias, const float* __restrict__ rowvec, int M)
{
    const int K = 128;
    const int N = (MODE == 0) ? 128 : 384;
    const bool B_NK = (MODE != 0);
    const float* __restrict__ A = (MODE == 0) ? g_agg : (MODE == 1) ? g_ws : Aparam;
    float* __restrict__ C = (MODE == 0) ? g_ws : (MODE == 1) ? g_gi : g_gh;

    __shared__ alignas(16) float sA[32 * 132];
    __shared__ alignas(16) float sB[32 * 132];
    int tid = threadIdx.x;
    int m0 = blockIdx.x * 128;
    int n0 = blockIdx.y * 128;
    int tx = tid & 15, ty = tid >> 4;

    float acc[8][8];
#pragma unroll
    for (int i = 0; i < 8; i++)
#pragma unroll
        for (int j = 0; j < 8; j++) acc[i][j] = 0.f;

#pragma unroll 1
    for (int kc = 0; kc < K; kc += 32) {
        __syncthreads();
        {   // stage A transposed: sA[k][m]
            int col4 = (tid & 7) * 4;
            int rowb = tid >> 3;
#pragma unroll
            for (int p = 0; p < 4; p++) {
                int r = rowb + p * 32;
                float4 v = make_float4(0.f, 0.f, 0.f, 0.f);
                if (m0 + r < M)
                    v = *reinterpret_cast<const float4*>(&A[(m0 + r) * K + kc + col4]);
                sA[(col4 + 0) * 132 + r] = v.x;
                sA[(col4 + 1) * 132 + r] = v.y;
                sA[(col4 + 2) * 132 + r] = v.z;
                sA[(col4 + 3) * 132 + r] = v.w;
            }
        }
        if (!B_NK) {   // B [K x N]
            int n4 = (tid & 31) * 4;
            int kr = tid >> 5;
#pragma unroll
            for (int p = 0; p < 4; p++) {
                int k = kr + p * 8;
                float4 v = *reinterpret_cast<const float4*>(&B[(kc + k) * N + n0 + n4]);
                *reinterpret_cast<float4*>(&sB[k * 132 + n4]) = v;
            }
        } else {       // B [N x K]
            int k4 = (tid & 7) * 4;
            int nr = tid >> 3;
#pragma unroll
            for (int p = 0; p < 4; p++) {
                int n = nr + p * 32;
                float4 v = *reinterpret_cast<const float4*>(&B[(n0 + n) * K + kc + k4]);
                sB[(k4 + 0) * 132 + n] = v.x;
                sB[(k4 + 1) * 132 + n] = v.y;
                sB[(k4 + 2) * 132 + n] = v.z;
                sB[(k4 + 3) * 132 + n] = v.w;
            }
        }
        __syncthreads();
#pragma unroll 8
        for (int k = 0; k < 32; k++) {
            float4 a0 = *reinterpret_cast<const float4*>(&sA[k * 132 + ty * 8]);
            float4 a1 = *reinterpret_cast<const float4*>(&sA[k * 132 + ty * 8 + 4]);
            float4 b0 = *reinterpret_cast<const float4*>(&sB[k * 132 + tx * 8]);
            float4 b1 = *reinterpret_cast<const float4*>(&sB[k * 132 + tx * 8 + 4]);
            float av[8] = {a0.x, a0.y, a0.z, a0.w, a1.x, a1.y, a1.z, a1.w};
            float bv[8] = {b0.x, b0.y, b0.z, b0.w, b1.x, b1.y, b1.z, b1.w};
#pragma unroll
            for (int i = 0; i < 8; i++)
#pragma unroll
                for (int j = 0; j < 8; j++)
                    acc[i][j] = fmaf(av[i], bv[j], acc[i][j]);
        }
    }

#pragma unroll
    for (int i = 0; i < 8; i++) {
        int m = m0 + ty * 8 + i;
        if (m < M) {
            float rs = (MODE == 0) ? g_attsum[m] : 0.f;
#pragma unroll
            for (int j = 0; j < 8; j++) {
                int n = n0 + tx * 8 + j;
                float v = acc[i][j];
                if (MODE != 0) v += bias[n];
                else v += rs * rowvec[n];
                C[m * N + n] = v;
            }
        }
    }
}

// ---------------- fused GRU gates + LayerNorm + MLP + residual ----------------
__global__ __launch_bounds__(128) void gru_kernel(
    const float* __restrict__ ph,
    const float* __restrict__ lng, const float* __restrict__ lnb,
    const float* __restrict__ W1, const float* __restrict__ b1,
    const float* __restrict__ W2, const float* __restrict__ b2,
    float* __restrict__ out)
{
    __shared__ alignas(16) float sW1[128 * 64];
    __shared__ float sLN[128];
    __shared__ float sHID[64];
    __shared__ float sred[8];
    int tid = threadIdx.x;
    int lane = tid & 31, wid = tid >> 5;
    for (int i = tid; i < 128 * 64; i += 128) sW1[i] = W1[i];
    float gln = lng[tid], bln = lnb[tid], bb2 = b2[tid];

    int p0 = blockIdx.x * 16;
    int pend = (p0 + 16 < NP) ? p0 + 16 : NP;
    for (int p = p0; p < pend; p++) {
        __syncthreads();
        float h = ph[p * 128 + tid];
        const float* gip = g_gi + p * 384;
        const float* ghp = g_gh + p * 384;
        float ir = gip[tid], iz = gip[128 + tid], in_ = gip[256 + tid];
        float hr = ghp[tid], hz = ghp[128 + tid], hn = ghp[256 + tid];
        float r = 1.f / (1.f + expf(-(ir + hr)));
        float z = 1.f / (1.f + expf(-(iz + hz)));
        float n = tanhf(in_ + r * hn);
        float x = (1.f - z) * n + z * h;

        float s1 = x, s2 = x * x;
#pragma unroll
        for (int o = 16; o > 0; o >>= 1) {
            s1 += __shfl_down_sync(0xffffffffu, s1, o);
            s2 += __shfl_down_sync(0xffffffffu, s2, o);
        }
        if (lane == 0) { sred[wid] = s1; sred[4 + wid] = s2; }
        __syncthreads();
        float S1 = sred[0] + sred[1] + sred[2] + sred[3];
        float S2 = sred[4] + sred[5] + sred[6] + sred[7];
        float mu = S1 * (1.f / 128.f);
        float var = S2 * (1.f / 128.f) - mu * mu;
        float ln = (x - mu) * (1.f / sqrtf(var + 1e-5f)) * gln + bln;
        sLN[tid] = ln;
        __syncthreads();
        if (tid < 64) {
            float a = b1[tid];
#pragma unroll 8
            for (int k = 0; k < 128; k++) a = fmaf(sLN[k], sW1[k * 64 + tid], a);
            sHID[tid] = fmaxf(a, 0.f);
        }
        __syncthreads();
        float o = bb2;
#pragma unroll 8
        for (int j = 0; j < 64; j++) o = fmaf(sHID[j], W2[j * 128 + tid], o);
        out[p * 128 + tid] = h + o;
    }
}

// ---------------- launch ----------------
extern "C" void kernel_launch(void* const* d_in, const int* in_sizes, int n_in,
                              void* d_out, int out_size)
{
    const float* nodes = (const float*)d_in[0];
    const float* parts = (const float*)d_in[1];
    const float* grep  = (const float*)d_in[2];
    const int*   src   = (const int*)d_in[3];
    const int*   dst   = (const int*)d_in[4];
    const float* key_W = (const float*)d_in[5];
    const float* key_b = (const float*)d_in[6];
    /* val_W */ const float* val_W = (const float*)d_in[7];
    const float* val_b = (const float*)d_in[8];
    const float* q_W   = (const float*)d_in[9];
    const float* q_b   = (const float*)d_in[10];
    const float* W_ih  = (const float*)d_in[11];
    const float* W_hh  = (const float*)d_in[12];
    const float* b_ih  = (const float*)d_in[13];
    const float* b_hh  = (const float*)d_in[14];
    const float* ln_g  = (const float*)d_in[15];
    const float* ln_b  = (const float*)d_in[16];
    const float* W1    = (const float*)d_in[17];
    const float* b1    = (const float*)d_in[18];
    const float* W2    = (const float*)d_in[19];
    const float* b2    = (const float*)d_in[20];
    float* out = (float*)d_out;

    zero_cnt_kernel<<<(NP + 255) / 256, 256>>>();
    proj_kernel<128><<<(NN + 127) / 128, 128>>>(nodes, nodes, key_W, key_b, NN);
    proj_kernel<256><<<(NP + 127) / 128, 128>>>(parts, grep, q_W, q_b, NP);
    count_kernel<<<(NE + 255) / 256, 256>>>(dst);
    scan_kernel<<<1, 1024>>>();
    att_scatter_kernel<<<(NE + 255) / 256, 256>>>(src, dst);
    aggregate_kernel<<<NP, 128>>>(nodes);
    // gh is independent of the aggregation chain; ws -> gi are dependent
    {
        dim3 g2((NP + 127) / 128, 3);
        sgemm_kernel<2><<<g2, 256>>>(parts, W_hh, b_hh, nullptr, NP);
    }
    {
        dim3 g0((NP + 127) / 128, 1);
        sgemm_kernel<0><<<g0, 256>>>(nullptr, val_W, nullptr, val_b, NP);
    }
    {
        dim3 g1((NP + 127) / 128, 3);
        sgemm_kernel<1><<<g1, 256>>>(nullptr, W_ih, b_ih, nullptr, NP);
    }
    gru_kernel<<<(NP + 15) / 16, 128>>>(parts, ln_g, ln_b, W1, b1, W2, b2, out);
}